// round 1
// baseline (speedup 1.0000x reference)
#include <cuda_runtime.h>
#include <math.h>

#define Bn  4
#define Sn  4096
#define Dn  1024
#define TPn 16
#define TEn 64
#define DKn 128

// ---------------- scratch (no allocations allowed) ----------------
__device__ float g_Q [Bn*Sn*DKn];
__device__ float g_Kd[Bn*Sn*DKn];
__device__ float g_Vd[Bn*Sn*DKn];
__device__ float g_QT[Bn*Sn*DKn];
__device__ float g_T [Bn*DKn*DKn];
__device__ float g_m [Bn*Sn];
__device__ float g_l [Bn*Sn];

// ---------------- kernel 1: T_scaled per batch ----------------
__global__ void prep_T_kernel(const float* __restrict__ tp,
                              const float* __restrict__ Wt,
                              const float* __restrict__ bt) {
    __shared__ float sTP[TPn*TEn];
    __shared__ float sWt[TEn*DKn];
    __shared__ float sE [TPn*DKn];
    __shared__ float red[256];
    int b = blockIdx.x, tid = threadIdx.x;
    for (int i = tid; i < TPn*TEn; i += 256) sTP[i] = tp[b*TPn*TEn + i];
    for (int i = tid; i < TEn*DKn; i += 256) sWt[i] = Wt[i];
    __syncthreads();
    for (int i = tid; i < TPn*DKn; i += 256) {
        int t = i >> 7, d = i & 127;
        float acc = bt[d];
        #pragma unroll 8
        for (int e = 0; e < TEn; e++) acc += sTP[t*TEn + e] * sWt[e*DKn + d];
        sE[i] = acc;
    }
    __syncthreads();
    float ss = 0.f;
    for (int i = tid; i < TPn*DKn; i += 256) ss += sE[i]*sE[i];
    red[tid] = ss; __syncthreads();
    for (int off = 128; off > 0; off >>= 1) {
        if (tid < off) red[tid] += red[tid+off];
        __syncthreads();
    }
    float tn = sqrtf((float)Sn * red[0]);
    float sc = (float)Sn / (tn + 1e-8f);
    for (int i = tid; i < DKn*DKn; i += 256) {
        int d = i >> 7, e2 = i & 127;
        float acc = 0.f;
        #pragma unroll
        for (int t = 0; t < TPn; t++) acc += sE[t*DKn + d] * sE[t*DKn + e2];
        g_T[b*DKn*DKn + i] = acc * sc;
    }
}

// ---------------- kernel 2: generic GEMM, N fixed = 128 ----------------
// C[M,128] = A[M,Kd] @ W[Kd,128] (+ bias). blockIdx.z batches via strides.
__global__ void gemm_n128(const float* __restrict__ A, const float* __restrict__ W,
                          const float* __restrict__ bias, float* __restrict__ C,
                          int M, int Kd, long long Ab, long long Wb, long long Cb) {
    A += (long long)blockIdx.z * Ab;
    W += (long long)blockIdx.z * Wb;
    C += (long long)blockIdx.z * Cb;
    __shared__ float sA[16*65];
    __shared__ float sW[16*128];
    int tid = threadIdx.x;
    int tr = tid >> 4, tc = tid & 15;      // 16x16 thread grid, 4x8 microtile
    int row0 = blockIdx.x << 6;
    float acc[4][8];
    #pragma unroll
    for (int i = 0; i < 4; i++)
        #pragma unroll
        for (int j = 0; j < 8; j++) acc[i][j] = 0.f;

    int kl = tid & 15, rb2 = tid >> 4;
    for (int k0 = 0; k0 < Kd; k0 += 16) {
        #pragma unroll
        for (int it = 0; it < 4; it++) {
            int rl = rb2 + (it << 4);
            sA[kl*65 + rl] = A[(long long)(row0 + rl)*Kd + (k0 + kl)];
        }
        #pragma unroll
        for (int i2 = tid; i2 < 2048; i2 += 256)
            sW[i2] = W[(long long)(k0 + (i2 >> 7))*DKn + (i2 & 127)];
        __syncthreads();
        #pragma unroll
        for (int k = 0; k < 16; k++) {
            float a[4];
            #pragma unroll
            for (int i = 0; i < 4; i++) a[i] = sA[k*65 + 4*tr + i];
            float4 w0 = *(const float4*)(sW + k*128 + 8*tc);
            float4 w1 = *(const float4*)(sW + k*128 + 8*tc + 4);
            float w[8] = {w0.x,w0.y,w0.z,w0.w,w1.x,w1.y,w1.z,w1.w};
            #pragma unroll
            for (int i = 0; i < 4; i++)
                #pragma unroll
                for (int j = 0; j < 8; j++) acc[i][j] += a[i]*w[j];
        }
        __syncthreads();
    }
    float bvv[8];
    if (bias) {
        float4 b0 = *(const float4*)(bias + 8*tc);
        float4 b1 = *(const float4*)(bias + 8*tc + 4);
        bvv[0]=b0.x; bvv[1]=b0.y; bvv[2]=b0.z; bvv[3]=b0.w;
        bvv[4]=b1.x; bvv[5]=b1.y; bvv[6]=b1.z; bvv[7]=b1.w;
    } else {
        #pragma unroll
        for (int j = 0; j < 8; j++) bvv[j] = 0.f;
    }
    #pragma unroll
    for (int i = 0; i < 4; i++) {
        long long row = row0 + 4*tr + i;
        float4 o0 = make_float4(acc[i][0]+bvv[0], acc[i][1]+bvv[1], acc[i][2]+bvv[2], acc[i][3]+bvv[3]);
        float4 o1 = make_float4(acc[i][4]+bvv[4], acc[i][5]+bvv[5], acc[i][6]+bvv[6], acc[i][7]+bvv[7]);
        *(float4*)(C + row*DKn + 8*tc)     = o0;
        *(float4*)(C + row*DKn + 8*tc + 4) = o1;
    }
}

// ---------------- kernel 3: flash attention + raw score dump ----------------
// grid (S/64, B), 256 threads. smem: sQ/sK k-major swizzled (pitch 68),
// sV row-major, sP probability tile.
#define PITCH 68
#define ATTN_SMEM ((128*PITCH + 128*PITCH + 64*128 + 64*PITCH) * 4)

__global__ void attn_kernel(float* __restrict__ d_out) {
    extern __shared__ float smem[];
    float* sQ = smem;                    // [128][68] k-major, swizzled cols
    float* sK = sQ + 128*PITCH;          // [128][68]
    float* sV = sK + 128*PITCH;          // [64][128] row-major
    float* sP = sV + 64*128;             // [64][68]

    int b  = blockIdx.y, rb = blockIdx.x;
    int tid = threadIdx.x;
    int tr = tid >> 4, tc = tid & 15;    // scores: 4 rows x 4 cols; out: 4 rows x 8 cols
    float* out  = d_out;
    float* attn = d_out + (long long)Bn*Sn*DKn;

    // ---- load QT block (64 rows x 128 dk), transpose to k-major with swizzle ----
    {
        const float* src = g_QT + ((long long)b*Sn + rb*64)*DKn;
        int m = tid & 31, r0 = tid >> 5;
        int k4 = 4*m, h = (m >> 1) & 7;   // h == ((k4+i)>>3)&7 for i in 0..3
        #pragma unroll
        for (int it = 0; it < 8; it++) {
            int r = r0 + it*8;
            float4 v = *(const float4*)(src + (long long)r*DKn + k4);
            int cs = (r & 3) | ((((r >> 2) ^ h) & 15) << 2);
            sQ[(k4+0)*PITCH + cs] = v.x;
            sQ[(k4+1)*PITCH + cs] = v.y;
            sQ[(k4+2)*PITCH + cs] = v.z;
            sQ[(k4+3)*PITCH + cs] = v.w;
        }
    }

    float m_r[4], l_r[4], acc[4][8];
    #pragma unroll
    for (int i = 0; i < 4; i++) {
        m_r[i] = -1e30f; l_r[i] = 0.f;
        #pragma unroll
        for (int j = 0; j < 8; j++) acc[i][j] = 0.f;
    }
    __syncthreads();

    const float scale = 0.08838834764831845f;  // 1/sqrt(128)

    for (int jt = 0; jt < Sn/64; jt++) {
        __syncthreads();   // previous tile's sK/sV/sP consumers done
        // ---- load K tile (transposed+swizzled) and V tile (row-major) ----
        {
            const float* srcK = g_Kd + ((long long)b*Sn + jt*64)*DKn;
            int m = tid & 31, r0 = tid >> 5;
            int k4 = 4*m, h = (m >> 1) & 7;
            #pragma unroll
            for (int it = 0; it < 8; it++) {
                int c = r0 + it*8;
                float4 v = *(const float4*)(srcK + (long long)c*DKn + k4);
                int cs = (c & 3) | ((((c >> 2) ^ h) & 15) << 2);
                sK[(k4+0)*PITCH + cs] = v.x;
                sK[(k4+1)*PITCH + cs] = v.y;
                sK[(k4+2)*PITCH + cs] = v.z;
                sK[(k4+3)*PITCH + cs] = v.w;
            }
            const float4* srcV = (const float4*)(g_Vd + ((long long)b*Sn + jt*64)*DKn);
            #pragma unroll
            for (int i2 = tid; i2 < 64*128/4; i2 += 256)
                ((float4*)sV)[i2] = srcV[i2];
        }
        __syncthreads();

        // ---- scores: 4x4 per thread over full K=128 ----
        float sc[4][4];
        #pragma unroll
        for (int i = 0; i < 4; i++)
            #pragma unroll
            for (int j = 0; j < 4; j++) sc[i][j] = 0.f;
        #pragma unroll 16
        for (int k = 0; k < DKn; k++) {
            int g = (k >> 3) & 7;
            float4 a4 = *(const float4*)(sQ + k*PITCH + (((tr ^ g) & 15) << 2));
            float4 b4 = *(const float4*)(sK + k*PITCH + (((tc ^ g) & 15) << 2));
            float a[4] = {a4.x,a4.y,a4.z,a4.w};
            float bb[4] = {b4.x,b4.y,b4.z,b4.w};
            #pragma unroll
            for (int i = 0; i < 4; i++)
                #pragma unroll
                for (int j = 0; j < 4; j++) sc[i][j] += a[i]*bb[j];
        }
        #pragma unroll
        for (int i = 0; i < 4; i++)
            #pragma unroll
            for (int j = 0; j < 4; j++) sc[i][j] *= scale;

        // ---- dump raw (scaled) scores to gmem attn region ----
        {
            long long base = (long long)b*Sn*Sn + (long long)(rb*64)*Sn + (long long)jt*64;
            #pragma unroll
            for (int i = 0; i < 4; i++) {
                long long row = 4*tr + i;
                *(float4*)(attn + base + row*Sn + 4*tc) =
                    make_float4(sc[i][0], sc[i][1], sc[i][2], sc[i][3]);
            }
        }

        // ---- online softmax update ----
        #pragma unroll
        for (int i = 0; i < 4; i++) {
            float rm = fmaxf(fmaxf(sc[i][0], sc[i][1]), fmaxf(sc[i][2], sc[i][3]));
            rm = fmaxf(rm, __shfl_xor_sync(0xffffffffu, rm, 1));
            rm = fmaxf(rm, __shfl_xor_sync(0xffffffffu, rm, 2));
            rm = fmaxf(rm, __shfl_xor_sync(0xffffffffu, rm, 4));
            rm = fmaxf(rm, __shfl_xor_sync(0xffffffffu, rm, 8));
            float mn   = fmaxf(m_r[i], rm);
            float resc = __expf(m_r[i] - mn);
            m_r[i] = mn;
            float rs = 0.f;
            #pragma unroll
            for (int j = 0; j < 4; j++) { sc[i][j] = __expf(sc[i][j] - mn); rs += sc[i][j]; }
            rs += __shfl_xor_sync(0xffffffffu, rs, 1);
            rs += __shfl_xor_sync(0xffffffffu, rs, 2);
            rs += __shfl_xor_sync(0xffffffffu, rs, 4);
            rs += __shfl_xor_sync(0xffffffffu, rs, 8);
            l_r[i] = l_r[i]*resc + rs;
            #pragma unroll
            for (int j = 0; j < 8; j++) acc[i][j] *= resc;
            *(float4*)(sP + (4*tr + i)*PITCH + 4*tc) =
                make_float4(sc[i][0], sc[i][1], sc[i][2], sc[i][3]);
        }
        __syncthreads();

        // ---- PV accumulation ----
        #pragma unroll 2
        for (int c4 = 0; c4 < 64; c4 += 4) {
            float p[4][4];
            #pragma unroll
            for (int i = 0; i < 4; i++) {
                float4 pv = *(const float4*)(sP + (4*tr + i)*PITCH + c4);
                p[i][0]=pv.x; p[i][1]=pv.y; p[i][2]=pv.z; p[i][3]=pv.w;
            }
            #pragma unroll
            for (int cc = 0; cc < 4; cc++) {
                float4 v0 = *(const float4*)(sV + (c4+cc)*128 + 8*tc);
                float4 v1 = *(const float4*)(sV + (c4+cc)*128 + 8*tc + 4);
                float v[8] = {v0.x,v0.y,v0.z,v0.w,v1.x,v1.y,v1.z,v1.w};
                #pragma unroll
                for (int i = 0; i < 4; i++) {
                    float pp = p[i][cc];
                    #pragma unroll
                    for (int j = 0; j < 8; j++) acc[i][j] += pp * v[j];
                }
            }
        }
    }

    // ---- epilogue: out = acc / l ; store m,l for normalize pass ----
    #pragma unroll
    for (int i = 0; i < 4; i++) {
        float inv = 1.0f / l_r[i];
        int row = rb*64 + 4*tr + i;
        float4 o0 = make_float4(acc[i][0]*inv, acc[i][1]*inv, acc[i][2]*inv, acc[i][3]*inv);
        float4 o1 = make_float4(acc[i][4]*inv, acc[i][5]*inv, acc[i][6]*inv, acc[i][7]*inv);
        long long obase = ((long long)b*Sn + row)*DKn;
        *(float4*)(out + obase + 8*tc)     = o0;
        *(float4*)(out + obase + 8*tc + 4) = o1;
        if (tc == 0) { g_m[b*Sn + row] = m_r[i]; g_l[b*Sn + row] = l_r[i]; }
    }
}

// ---------------- kernel 4: in-place softmax normalize of attn ----------------
__global__ void softmax_norm_kernel(float* __restrict__ attn) {
    long long total4 = (long long)Bn*Sn*Sn / 4;
    long long stride = (long long)gridDim.x * blockDim.x;
    for (long long idx = (long long)blockIdx.x*blockDim.x + threadIdx.x;
         idx < total4; idx += stride) {
        long long e = idx << 2;
        int row = (int)(e >> 12);          // S = 4096 cols per row; row in [0, B*S)
        float mm  = g_m[row];
        float inv = 1.0f / g_l[row];
        float4 v = ((float4*)attn)[idx];
        v.x = __expf(v.x - mm) * inv;
        v.y = __expf(v.y - mm) * inv;
        v.z = __expf(v.z - mm) * inv;
        v.w = __expf(v.w - mm) * inv;
        ((float4*)attn)[idx] = v;
    }
}

// ---------------- launcher ----------------
extern "C" void kernel_launch(void* const* d_in, const int* in_sizes, int n_in,
                              void* d_out, int out_size) {
    const float* x  = (const float*)d_in[0];
    const float* tp = (const float*)d_in[1];
    const float* Wq = (const float*)d_in[2];
    const float* bq = (const float*)d_in[3];
    const float* Wk = (const float*)d_in[4];
    const float* bk = (const float*)d_in[5];
    const float* Wv = (const float*)d_in[6];
    const float* bv = (const float*)d_in[7];
    const float* Wt = (const float*)d_in[8];
    const float* bt = (const float*)d_in[9];
    float* out = (float*)d_out;

    float *pQ, *pK, *pV, *pQT, *pT;
    cudaGetSymbolAddress((void**)&pQ,  g_Q);
    cudaGetSymbolAddress((void**)&pK,  g_Kd);
    cudaGetSymbolAddress((void**)&pV,  g_Vd);
    cudaGetSymbolAddress((void**)&pQT, g_QT);
    cudaGetSymbolAddress((void**)&pT,  g_T);

    cudaFuncSetAttribute(attn_kernel, cudaFuncAttributeMaxDynamicSharedMemorySize, ATTN_SMEM);

    // 1) T_scaled
    prep_T_kernel<<<Bn, 256>>>(tp, Wt, bt);
    // 2) Q, K, V projections (M = B*S, Kd = D)
    gemm_n128<<<dim3((Bn*Sn)/64, 1, 1), 256>>>(x, Wq, bq, pQ, Bn*Sn, Dn, 0, 0, 0);
    gemm_n128<<<dim3((Bn*Sn)/64, 1, 1), 256>>>(x, Wk, bk, pK, Bn*Sn, Dn, 0, 0, 0);
    gemm_n128<<<dim3((Bn*Sn)/64, 1, 1), 256>>>(x, Wv, bv, pV, Bn*Sn, Dn, 0, 0, 0);
    // 3) QT = Q @ T_scaled (per batch)
    gemm_n128<<<dim3(Sn/64, 1, Bn), 256>>>(pQ, pT, nullptr, pQT, Sn, DKn,
                                           (long long)Sn*DKn, (long long)DKn*DKn,
                                           (long long)Sn*DKn);
    // 4) flash attention + raw score dump + out
    attn_kernel<<<dim3(Sn/64, Bn), 256, ATTN_SMEM>>>(out);
    // 5) normalize attn in place
    softmax_norm_kernel<<<4096, 256>>>(out + (long long)Bn*Sn*DKn);
}